// round 3
// baseline (speedup 1.0000x reference)
#include <cuda_runtime.h>
#include <math.h>

#define N_NODES 100000
#define N_EDGES 1600000
#define HID 128
#define EPS 1e-5f

// ---------------- scratch (device globals; referenced ONLY in device code) ----------------
__device__ float  d_h0[N_NODES * HID];
__device__ float  d_h1[N_NODES * HID];
__device__ float  d_g [N_NODES * HID];   // dinv-scaled h@W ; head reuses as ff[N,32]
__device__ float  d_agg[N_NODES * HID];
__device__ float  d_dinv[N_NODES];
__device__ int    d_cnt[N_NODES];
__device__ int    d_cursor[N_NODES];
__device__ int    d_rowptr[N_NODES + 1];
__device__ int    d_col[N_EDGES];
__device__ int    d_bsums[128];
__device__ double d_bnSum[HID];
__device__ double d_bnSqs[HID];
__device__ float  d_bnA[HID];
__device__ float  d_bnC[HID];

// ---------------- helpers ----------------
__device__ __forceinline__ void fma4(float4& a, float s, const float4& w) {
    a.x = fmaf(s, w.x, a.x);
    a.y = fmaf(s, w.y, a.y);
    a.z = fmaf(s, w.z, a.z);
    a.w = fmaf(s, w.w, a.w);
}
__device__ __forceinline__ void add4(float4& a, const float4& v) {
    a.x += v.x; a.y += v.y; a.z += v.z; a.w += v.w;
}
__device__ __forceinline__ float* hbuf(int sel) { return sel == 0 ? d_h0 : d_h1; }

// ---------------- setup kernels ----------------
__global__ void k_zero_counts() {
    int i = blockIdx.x * blockDim.x + threadIdx.x;
    if (i < N_NODES) { d_cnt[i] = 0; d_cursor[i] = 0; }
}
__global__ void k_zero_bn() {
    int t = threadIdx.x;
    if (t < HID) { d_bnSum[t] = 0.0; d_bnSqs[t] = 0.0; }
}
__global__ void k_count(const int* __restrict__ ei) {
    int e = blockIdx.x * blockDim.x + threadIdx.x;
    if (e < N_EDGES) atomicAdd(&d_cnt[ei[N_EDGES + e]], 1);
}
__global__ void k_dinv() {
    int i = blockIdx.x * blockDim.x + threadIdx.x;
    if (i < N_NODES) d_dinv[i] = rsqrtf((float)d_cnt[i] + 1.0f);
}
__global__ void k_scan_local() {
    __shared__ int s[1024];
    int tid = threadIdx.x;
    int idx = blockIdx.x * 1024 + tid;
    int v = (idx < N_NODES) ? d_cnt[idx] : 0;
    s[tid] = v;
    __syncthreads();
    for (int off = 1; off < 1024; off <<= 1) {
        int t = (tid >= off) ? s[tid - off] : 0;
        __syncthreads();
        s[tid] += t;
        __syncthreads();
    }
    if (idx < N_NODES) d_rowptr[idx] = s[tid] - v;   // exclusive
    if (tid == 1023) d_bsums[blockIdx.x] = s[1023];
}
__global__ void k_scan_bsums(int nb) {
    __shared__ int sb[128];
    int t = threadIdx.x;
    sb[t] = (t < nb) ? d_bsums[t] : 0;
    __syncthreads();
    if (t == 0) {
        int run = 0;
        for (int i = 0; i < nb; i++) { int x = sb[i]; sb[i] = run; run += x; }
        d_rowptr[N_NODES] = run;
    }
    __syncthreads();
    if (t < nb) d_bsums[t] = sb[t];
}
__global__ void k_scan_add() {
    int idx = blockIdx.x * 1024 + threadIdx.x;
    if (idx < N_NODES) d_rowptr[idx] += d_bsums[blockIdx.x];
}
__global__ void k_fill(const int* __restrict__ ei) {
    int e = blockIdx.x * blockDim.x + threadIdx.x;
    if (e < N_EDGES) {
        int s = ei[e];
        int d = ei[N_EDGES + e];
        int pos = d_rowptr[d] + atomicAdd(&d_cursor[d], 1);
        d_col[pos] = s;
    }
}

// ---------------- encoder: h0 = relu(x @ We + be) ----------------
__global__ void k_encoder(const float* __restrict__ x,
                          const float* __restrict__ We,
                          const float* __restrict__ be) {
    int gt = blockIdx.x * blockDim.x + threadIdx.x;
    if (gt >= N_NODES * 32) return;
    int i = gt >> 5, l = gt & 31;
    float x0 = __ldg(&x[2 * i]), x1 = __ldg(&x[2 * i + 1]);
    float4 w0 = __ldg(&((const float4*)We)[l]);
    float4 w1 = __ldg(&((const float4*)We)[32 + l]);
    float4 b  = __ldg(&((const float4*)be)[l]);
    float4 h;
    h.x = fmaxf(fmaf(x0, w0.x, fmaf(x1, w1.x, b.x)), 0.f);
    h.y = fmaxf(fmaf(x0, w0.y, fmaf(x1, w1.y, b.y)), 0.f);
    h.z = fmaxf(fmaf(x0, w0.z, fmaf(x1, w1.z, b.z)), 0.f);
    h.w = fmaxf(fmaf(x0, w0.w, fmaf(x1, w1.w, b.w)), 0.f);
    ((float4*)d_h0)[gt] = h;
}

// ---------------- d_g = dinv[i] * (h[sel] @ W), 128x128 GEMM ----------------
// warp computes 4 nodes x 128 outputs; each W row load feeds 16 FMAs
__global__ void k_gemm128(const float* __restrict__ W, int hin_sel) {
    const int lane = threadIdx.x & 31;
    const int gwid = (blockIdx.x * blockDim.x + threadIdx.x) >> 5;
    const int nwarps = (gridDim.x * blockDim.x) >> 5;
    const float4* W4 = reinterpret_cast<const float4*>(W);
    const float4* H4 = reinterpret_cast<const float4*>(hbuf(hin_sel));
    float4* O4 = reinterpret_cast<float4*>(d_g);

    for (int base = gwid * 4; base < N_NODES; base += nwarps * 4) {
        const float4 z = make_float4(0.f, 0.f, 0.f, 0.f);
        float4 h0 = H4[(size_t)base * 32 + lane];
        float4 h1 = H4[(size_t)(base + 1) * 32 + lane];
        float4 h2 = H4[(size_t)(base + 2) * 32 + lane];
        float4 h3 = H4[(size_t)(base + 3) * 32 + lane];
        float4 a0 = z, a1 = z, a2 = z, a3 = z;

        #pragma unroll 8
        for (int q = 0; q < 32; q++) {
            float4 w0 = __ldg(&W4[(q * 4 + 0) * 32 + lane]);
            float4 w1 = __ldg(&W4[(q * 4 + 1) * 32 + lane]);
            float4 w2 = __ldg(&W4[(q * 4 + 2) * 32 + lane]);
            float4 w3 = __ldg(&W4[(q * 4 + 3) * 32 + lane]);
            {
                float sx = __shfl_sync(0xffffffffu, h0.x, q);
                float sy = __shfl_sync(0xffffffffu, h0.y, q);
                float sz = __shfl_sync(0xffffffffu, h0.z, q);
                float sw = __shfl_sync(0xffffffffu, h0.w, q);
                fma4(a0, sx, w0); fma4(a0, sy, w1); fma4(a0, sz, w2); fma4(a0, sw, w3);
            }
            {
                float sx = __shfl_sync(0xffffffffu, h1.x, q);
                float sy = __shfl_sync(0xffffffffu, h1.y, q);
                float sz = __shfl_sync(0xffffffffu, h1.z, q);
                float sw = __shfl_sync(0xffffffffu, h1.w, q);
                fma4(a1, sx, w0); fma4(a1, sy, w1); fma4(a1, sz, w2); fma4(a1, sw, w3);
            }
            {
                float sx = __shfl_sync(0xffffffffu, h2.x, q);
                float sy = __shfl_sync(0xffffffffu, h2.y, q);
                float sz = __shfl_sync(0xffffffffu, h2.z, q);
                float sw = __shfl_sync(0xffffffffu, h2.w, q);
                fma4(a2, sx, w0); fma4(a2, sy, w1); fma4(a2, sz, w2); fma4(a2, sw, w3);
            }
            {
                float sx = __shfl_sync(0xffffffffu, h3.x, q);
                float sy = __shfl_sync(0xffffffffu, h3.y, q);
                float sz = __shfl_sync(0xffffffffu, h3.z, q);
                float sw = __shfl_sync(0xffffffffu, h3.w, q);
                fma4(a3, sx, w0); fma4(a3, sy, w1); fma4(a3, sz, w2); fma4(a3, sw, w3);
            }
        }
        {
            float s = d_dinv[base];
            a0.x *= s; a0.y *= s; a0.z *= s; a0.w *= s;
            O4[(size_t)base * 32 + lane] = a0;
        }
        {
            float s = d_dinv[base + 1];
            a1.x *= s; a1.y *= s; a1.z *= s; a1.w *= s;
            O4[(size_t)(base + 1) * 32 + lane] = a1;
        }
        {
            float s = d_dinv[base + 2];
            a2.x *= s; a2.y *= s; a2.z *= s; a2.w *= s;
            O4[(size_t)(base + 2) * 32 + lane] = a2;
        }
        {
            float s = d_dinv[base + 3];
            a3.x *= s; a3.y *= s; a3.z *= s; a3.w *= s;
            O4[(size_t)(base + 3) * 32 + lane] = a3;
        }
    }
}

// ---------------- aggregation: agg[i] = dinv[i]*(sum_in g[src] + g[i]); BN partials ---
__global__ void k_aggregate() {
    __shared__ float sS[HID];
    __shared__ float sQ[HID];
    if (threadIdx.x < HID) { sS[threadIdx.x] = 0.f; sQ[threadIdx.x] = 0.f; }
    __syncthreads();

    const int lane = threadIdx.x & 31;
    const int gwid = (blockIdx.x * blockDim.x + threadIdx.x) >> 5;
    const int nwarps = (gridDim.x * blockDim.x) >> 5;
    const float4* g4 = reinterpret_cast<const float4*>(d_g);
    float4* agg4 = reinterpret_cast<float4*>(d_agg);

    float4 lsum = make_float4(0.f, 0.f, 0.f, 0.f);
    float4 lsq  = make_float4(0.f, 0.f, 0.f, 0.f);

    for (int i = gwid; i < N_NODES; i += nwarps) {
        float4 acc = g4[(size_t)i * 32 + lane];   // self loop
        int e0 = d_rowptr[i], e1 = d_rowptr[i + 1];
        for (int e = e0; e < e1; e++) {
            int s = __ldg(&d_col[e]);
            float4 v = __ldg(&g4[(size_t)s * 32 + lane]);
            add4(acc, v);
        }
        float dv = d_dinv[i];
        acc.x *= dv; acc.y *= dv; acc.z *= dv; acc.w *= dv;
        agg4[(size_t)i * 32 + lane] = acc;
        add4(lsum, acc);
        lsq.x = fmaf(acc.x, acc.x, lsq.x);
        lsq.y = fmaf(acc.y, acc.y, lsq.y);
        lsq.z = fmaf(acc.z, acc.z, lsq.z);
        lsq.w = fmaf(acc.w, acc.w, lsq.w);
    }
    int f = 4 * lane;
    atomicAdd(&sS[f + 0], lsum.x); atomicAdd(&sS[f + 1], lsum.y);
    atomicAdd(&sS[f + 2], lsum.z); atomicAdd(&sS[f + 3], lsum.w);
    atomicAdd(&sQ[f + 0], lsq.x);  atomicAdd(&sQ[f + 1], lsq.y);
    atomicAdd(&sQ[f + 2], lsq.z);  atomicAdd(&sQ[f + 3], lsq.w);
    __syncthreads();
    if (threadIdx.x < HID) {
        atomicAdd(&d_bnSum[threadIdx.x], (double)sS[threadIdx.x]);
        atomicAdd(&d_bnSqs[threadIdx.x], (double)sQ[threadIdx.x]);
    }
}

// ---------------- BN coeffs: a = gamma*rsqrt(var+eps), c = beta - mean*a ----------------
__global__ void k_bn_finalize(const float* __restrict__ gamma,
                              const float* __restrict__ beta, int nfeat) {
    int t = threadIdx.x;
    if (t < nfeat) {
        double mean = d_bnSum[t] / (double)N_NODES;
        double var  = d_bnSqs[t] / (double)N_NODES - mean * mean;
        float a = gamma[t] * rsqrtf((float)var + EPS);
        d_bnA[t] = a;
        d_bnC[t] = beta[t] - (float)mean * a;
    }
}

// ---------------- h[hout] = relu(a*agg + c) + h[hin] ----------------
__global__ void k_bnrelu_res(int hin_sel, int hout_sel) {
    int gt = blockIdx.x * blockDim.x + threadIdx.x;
    if (gt >= N_NODES * 32) return;
    int l = gt & 31;
    float4 a = ((const float4*)d_bnA)[l];
    float4 c = ((const float4*)d_bnC)[l];
    float4 v = ((const float4*)d_agg)[gt];
    float4 h = ((const float4*)hbuf(hin_sel))[gt];
    float4 r;
    r.x = fmaxf(fmaf(a.x, v.x, c.x), 0.f) + h.x;
    r.y = fmaxf(fmaf(a.y, v.y, c.y), 0.f) + h.y;
    r.z = fmaxf(fmaf(a.z, v.z, c.z), 0.f) + h.z;
    r.w = fmaxf(fmaf(a.w, v.w, c.w), 0.f) + h.w;
    ((float4*)hbuf(hout_sel))[gt] = r;
}

// ---------------- ff = h[sel] @ Wf1  (128 -> 32), stored in d_g ----------------
__global__ void k_gemm32(const float* __restrict__ W, int hin_sel) {
    __shared__ float sW[HID * 32];
    for (int i = threadIdx.x; i < HID * 32; i += blockDim.x) sW[i] = W[i];
    __syncthreads();
    const int lane = threadIdx.x & 31;
    const int gwid = (blockIdx.x * blockDim.x + threadIdx.x) >> 5;
    const int nwarps = (gridDim.x * blockDim.x) >> 5;
    const float4* H4 = reinterpret_cast<const float4*>(hbuf(hin_sel));
    for (int i = gwid; i < N_NODES; i += nwarps) {
        float4 h = H4[(size_t)i * 32 + lane];
        float acc = 0.f;
        #pragma unroll 8
        for (int q = 0; q < 32; q++) {
            float sx = __shfl_sync(0xffffffffu, h.x, q);
            float sy = __shfl_sync(0xffffffffu, h.y, q);
            float sz = __shfl_sync(0xffffffffu, h.z, q);
            float sw = __shfl_sync(0xffffffffu, h.w, q);
            acc = fmaf(sx, sW[(4 * q + 0) * 32 + lane], acc);
            acc = fmaf(sy, sW[(4 * q + 1) * 32 + lane], acc);
            acc = fmaf(sz, sW[(4 * q + 2) * 32 + lane], acc);
            acc = fmaf(sw, sW[(4 * q + 3) * 32 + lane], acc);
        }
        d_g[(size_t)i * 32 + lane] = acc;
    }
}

// ---------------- BN stats over ff[N,32] (in d_g) ----------------
__global__ void k_bnstats32() {
    __shared__ float sS[32];
    __shared__ float sQ[32];
    if (threadIdx.x < 32) { sS[threadIdx.x] = 0.f; sQ[threadIdx.x] = 0.f; }
    __syncthreads();
    const int lane = threadIdx.x & 31;
    const int gwid = (blockIdx.x * blockDim.x + threadIdx.x) >> 5;
    const int nwarps = (gridDim.x * blockDim.x) >> 5;
    float s = 0.f, q = 0.f;
    for (int i = gwid; i < N_NODES; i += nwarps) {
        float v = d_g[(size_t)i * 32 + lane];
        s += v;
        q = fmaf(v, v, q);
    }
    atomicAdd(&sS[lane], s);
    atomicAdd(&sQ[lane], q);
    __syncthreads();
    if (threadIdx.x < 32) {
        atomicAdd(&d_bnSum[threadIdx.x], (double)sS[threadIdx.x]);
        atomicAdd(&d_bnSqs[threadIdx.x], (double)sQ[threadIdx.x]);
    }
}

// ---------------- out = tanh(relu(a*ff+c) @ Wf2 + bf2) ----------------
__global__ void k_out(const float* __restrict__ Wf2,
                      const float* __restrict__ bf2,
                      float* __restrict__ out) {
    __shared__ float sA[32], sC[32], sW[64], sB[2];
    int t = threadIdx.x;
    if (t < 32) { sA[t] = d_bnA[t]; sC[t] = d_bnC[t]; }
    if (t < 64) sW[t] = Wf2[t];
    if (t < 2) sB[t] = bf2[t];
    __syncthreads();
    int i = blockIdx.x * blockDim.x + t;
    if (i >= N_NODES) return;
    float a0 = sB[0], a1 = sB[1];
    const float4* f4 = reinterpret_cast<const float4*>(d_g + (size_t)i * 32);
    #pragma unroll
    for (int j4 = 0; j4 < 8; j4++) {
        float4 v = f4[j4];
        int j = j4 * 4;
        float f;
        f = fmaxf(fmaf(sA[j + 0], v.x, sC[j + 0]), 0.f); a0 = fmaf(f, sW[2 * (j + 0)], a0); a1 = fmaf(f, sW[2 * (j + 0) + 1], a1);
        f = fmaxf(fmaf(sA[j + 1], v.y, sC[j + 1]), 0.f); a0 = fmaf(f, sW[2 * (j + 1)], a0); a1 = fmaf(f, sW[2 * (j + 1) + 1], a1);
        f = fmaxf(fmaf(sA[j + 2], v.z, sC[j + 2]), 0.f); a0 = fmaf(f, sW[2 * (j + 2)], a0); a1 = fmaf(f, sW[2 * (j + 2) + 1], a1);
        f = fmaxf(fmaf(sA[j + 3], v.w, sC[j + 3]), 0.f); a0 = fmaf(f, sW[2 * (j + 3)], a0); a1 = fmaf(f, sW[2 * (j + 3) + 1], a1);
    }
    out[2 * i]     = tanhf(a0);
    out[2 * i + 1] = tanhf(a1);
}

// ---------------- launch ----------------
extern "C" void kernel_launch(void* const* d_in, const int* in_sizes, int n_in,
                              void* d_out, int out_size) {
    const float* x    = (const float*)d_in[0];
    const int*   ei   = (const int*)d_in[1];
    const float* We   = (const float*)d_in[2];
    const float* be   = (const float*)d_in[3];
    const float* W1   = (const float*)d_in[4];
    const float* g1   = (const float*)d_in[6];
    const float* bt1  = (const float*)d_in[7];
    const float* W2   = (const float*)d_in[8];
    const float* g2   = (const float*)d_in[10];
    const float* bt2  = (const float*)d_in[11];
    const float* W3   = (const float*)d_in[12];
    const float* g3   = (const float*)d_in[14];
    const float* bt3  = (const float*)d_in[15];
    const float* Wf1  = (const float*)d_in[16];
    const float* gf   = (const float*)d_in[18];
    const float* btf  = (const float*)d_in[19];
    const float* Wf2  = (const float*)d_in[20];
    const float* bf2  = (const float*)d_in[21];
    float* out = (float*)d_out;
    // (b1/b2/b3/bf1 unused: uniform per-feature bias cancels inside BatchNorm)

    const int nb_scan = (N_NODES + 1023) / 1024;   // 98

    // graph preprocessing: degree -> dinv, CSC build
    k_zero_counts<<<(N_NODES + 255) / 256, 256>>>();
    k_count<<<(N_EDGES + 255) / 256, 256>>>(ei);
    k_dinv<<<(N_NODES + 255) / 256, 256>>>();
    k_scan_local<<<nb_scan, 1024>>>();
    k_scan_bsums<<<1, 128>>>(nb_scan);
    k_scan_add<<<nb_scan, 1024>>>();
    k_fill<<<(N_EDGES + 255) / 256, 256>>>(ei);

    // encoder
    k_encoder<<<(N_NODES * 32 + 255) / 256, 256>>>(x, We, be);

    const int GB = 592;    // gemm/aggregate grid blocks (4 per SM)
    const int EW = (N_NODES * 32 + 255) / 256;

    // block 1: h0 -> h1
    k_zero_bn<<<1, 128>>>();
    k_gemm128<<<GB, 256>>>(W1, 0);
    k_aggregate<<<GB, 256>>>();
    k_bn_finalize<<<1, 128>>>(g1, bt1, HID);
    k_bnrelu_res<<<EW, 256>>>(0, 1);

    // block 2: h1 -> h0
    k_zero_bn<<<1, 128>>>();
    k_gemm128<<<GB, 256>>>(W2, 1);
    k_aggregate<<<GB, 256>>>();
    k_bn_finalize<<<1, 128>>>(g2, bt2, HID);
    k_bnrelu_res<<<EW, 256>>>(1, 0);

    // block 3: h0 -> h1
    k_zero_bn<<<1, 128>>>();
    k_gemm128<<<GB, 256>>>(W3, 0);
    k_aggregate<<<GB, 256>>>();
    k_bn_finalize<<<1, 128>>>(g3, bt3, HID);
    k_bnrelu_res<<<EW, 256>>>(0, 1);

    // head: ff = h3 @ Wf1; BN; out = tanh(relu(BN(ff)) @ Wf2 + bf2)
    k_zero_bn<<<1, 128>>>();
    k_gemm32<<<GB, 256>>>(Wf1, 1);
    k_bnstats32<<<296, 256>>>();
    k_bn_finalize<<<1, 128>>>(gf, btf, 32);
    k_out<<<(N_NODES + 127) / 128, 128>>>(Wf2, bf2, out);

    (void)in_sizes; (void)n_in; (void)out_size;
}